// round 5
// baseline (speedup 1.0000x reference)
#include <cuda_runtime.h>

// Problem constants (fixed by the dataset): S=8192, N=2048, D=128, C=256
constexpr int D_ = 128;
constexpr int C_ = 256;
constexpr int QB = 4;      // queries per block in main kernel

// Scratch (no allocations allowed)
__device__ __align__(16) float  g_mus[C_ * D_];        // class sums [c][d]
__device__ __align__(16) float4 g_mus4[(D_ / 4) * C_]; // transposed [d4][c] as float4
__device__ float                g_s2[C_];              // ||mus_c||^2
__device__ float                g_cnt[C_];             // class counts (float)
__device__ float                g_loss;                // sum of -logp
__device__ unsigned int         g_done;                // finished-block ticket

// Packed dual-lane FP32 FMA (sm_103a).
__device__ __forceinline__ unsigned long long ffma2(unsigned long long a,
                                                    unsigned long long b,
                                                    unsigned long long c) {
    unsigned long long d;
    asm("fma.rn.f32x2 %0, %1, %2, %3;" : "=l"(d) : "l"(a), "l"(b), "l"(c));
    return d;
}
__device__ __forceinline__ float f32x2_sum(unsigned long long v) {
    float lo, hi;
    asm("mov.b64 {%0, %1}, %2;" : "=f"(lo), "=f"(hi) : "l"(v));
    return lo + hi;
}

// ---------------------------------------------------------------- zero
__global__ void k_zero() {
    int i = blockIdx.x * blockDim.x + threadIdx.x;
    if (i < C_ * D_) g_mus[i] = 0.0f;
    if (i < C_)      g_cnt[i] = 0.0f;
    if (i == 0)      { g_loss = 0.0f; g_done = 0u; }
}

// ---------------------------------------------------------------- scatter class sums
// Labels are int32 (JAX x64-disabled downcast of the reference's int64).
__global__ void k_accum(const float* __restrict__ xs,
                        const int* __restrict__ ys) {
    int s = blockIdx.x * 2 + (threadIdx.x >> 7);
    int d = threadIdx.x & 127;
    int c = ys[s] & (C_ - 1);              // mask keeps scatter in-bounds
    atomicAdd(&g_mus[c * D_ + d], xs[(size_t)s * D_ + d]);
    if (d == 0) atomicAdd(&g_cnt[c], 1.0f);
}

// ---------------------------------------------------------------- stats + transpose
__global__ void k_stats() {
    int c = blockIdx.x;
    int d = threadIdx.x;
    float v = g_mus[c * D_ + d];
    if ((d & 3) == 0) {
        float4 val = *reinterpret_cast<const float4*>(&g_mus[c * D_ + d]);
        g_mus4[(d >> 2) * C_ + c] = val;
    }
    float p = v * v;
    #pragma unroll
    for (int o = 16; o; o >>= 1) p += __shfl_down_sync(0xffffffffu, p, o);
    __shared__ float sp[4];
    if ((d & 31) == 0) sp[d >> 5] = p;
    __syncthreads();
    if (d == 0) g_s2[c] = sp[0] + sp[1] + sp[2] + sp[3];
}

// ---------------------------------------------------------------- main
// 512 threads: thread = (h, c), h = dim-half, c = class. QB=4 queries/block,
// grid = 512 -> ~3.5 blocks/SM for latency hiding. g_mus4 is L1-resident.
// Last block to finish writes the output scalar.
__global__ void __launch_bounds__(512, 3) k_main(const float* __restrict__ xq,
                                                 const int* __restrict__ yq,
                                                 float* __restrict__ out,
                                                 int N) {
    __shared__ float4 xq_s[QB * D_ / 4];   // 2 KB
    __shared__ float  part_s[QB * C_];     // 4 KB: h=1 partial dots
    __shared__ float  logit_s[QB * C_];    // 4 KB
    __shared__ float  q2_s[QB];
    __shared__ int    y_s[QB];
    __shared__ float  warp_loss[QB];

    const int t  = threadIdx.x;
    const int c  = t & (C_ - 1);
    const int h  = t >> 8;                 // dim-half
    const int q0 = blockIdx.x * QB;

    if (t < QB) { q2_s[t] = 0.0f; y_s[t] = yq[q0 + t] & (C_ - 1); }
    __syncthreads();

    // Load the 4x128 query tile (float4) and accumulate ||xq||^2 per query.
    const float4* src = reinterpret_cast<const float4*>(xq + (size_t)q0 * D_);
    if (t < QB * D_ / 4) {
        float4 v = src[t];
        xq_s[t] = v;
        int q = (t * 4) / D_;
        atomicAdd(&q2_s[q], v.x * v.x + v.y * v.y + v.z * v.z + v.w * v.w);
    }

    // Per-class scalars (LDGs overlap mainloop wind-up; L1 hits).
    const float s2  = g_s2[c];
    const float cnt = g_cnt[c];
    __syncthreads();

    // Dot products over this thread's 64-dim half, packed f32x2.
    const ulonglong2* mus2 = reinterpret_cast<const ulonglong2*>(g_mus4);
    const ulonglong2* xs2  = reinterpret_cast<const ulonglong2*>(xq_s);

    unsigned long long acc[QB];
    #pragma unroll
    for (int q = 0; q < QB; q++) acc[q] = 0ull;

    const int d4_0 = h * (D_ / 8);         // 16 float4 chunks per half
    #pragma unroll 8
    for (int i = 0; i < D_ / 8; i++) {
        int d4 = d4_0 + i;
        ulonglong2 m = mus2[d4 * C_ + c];  // LDG.128, L1-resident
        #pragma unroll
        for (int q = 0; q < QB; q++) {
            ulonglong2 x = xs2[q * (D_ / 4) + d4];  // smem broadcast
            acc[q] = ffma2(m.x, x.x, acc[q]);
            acc[q] = ffma2(m.y, x.y, acc[q]);
        }
    }

    float dotq[QB];
    #pragma unroll
    for (int q = 0; q < QB; q++) dotq[q] = f32x2_sum(acc[q]);

    if (h == 1) {
        #pragma unroll
        for (int q = 0; q < QB; q++) part_s[q * C_ + c] = dotq[q];
    }
    __syncthreads();

    if (h == 0) {
        #pragma unroll
        for (int q = 0; q < QB; q++) {
            float q2  = q2_s[q];
            float dot = dotq[q] + part_s[q * C_ + c];
            float del = (y_s[q] == c) ? 1.0f : 0.0f;
            float xqM = dot - del * q2;
            float M2  = s2 - del * (2.0f * dot - q2);
            float cn  = cnt - del;
            float den = fmaxf(cn, 0.1f);
            float inv = 1.0f / den;
            float l   = -0.5f * (q2 - 2.0f * xqM * inv + M2 * inv * inv);
            logit_s[q * C_ + c] = (cn > 0.1f) ? l : 0.0f;
        }
    }
    __syncthreads();

    // Log-softmax: warp w (w < QB) handles query w.
    const int w = t >> 5, lane = t & 31;
    if (w < QB) {
        float vals[C_ / 32];
        float vmax = -1e30f;
        #pragma unroll
        for (int i = 0; i < C_ / 32; i++) {
            vals[i] = logit_s[w * C_ + lane + 32 * i];
            vmax = fmaxf(vmax, vals[i]);
        }
        #pragma unroll
        for (int o = 16; o; o >>= 1) vmax = fmaxf(vmax, __shfl_xor_sync(0xffffffffu, vmax, o));
        float se = 0.0f;
        #pragma unroll
        for (int i = 0; i < C_ / 32; i++) se += __expf(vals[i] - vmax);
        #pragma unroll
        for (int o = 16; o; o >>= 1) se += __shfl_xor_sync(0xffffffffu, se, o);
        if (lane == 0) {
            float ly = logit_s[w * C_ + y_s[w]];
            warp_loss[w] = (vmax + __logf(se)) - ly;   // -log p(target)
        }
    }
    __syncthreads();
    if (t == 0) {
        float s = 0.0f;
        #pragma unroll
        for (int i = 0; i < QB; i++) s += warp_loss[i];
        atomicAdd(&g_loss, s);
        __threadfence();
        unsigned int ticket = atomicAdd(&g_done, 1u);
        if (ticket == gridDim.x - 1) {      // last block: finalize
            out[0] = g_loss / (float)N;
        }
    }
}

// ---------------------------------------------------------------- launcher
extern "C" void kernel_launch(void* const* d_in, const int* in_sizes, int n_in,
                              void* d_out, int out_size) {
    const float* xq = (const float*)d_in[0];
    const int*   yq = (const int*)d_in[1];
    const float* xs = (const float*)d_in[2];
    const int*   ys = (const int*)d_in[3];
    // d_in[4] = pos (unused: yq == ys[pos] already)

    const int N = in_sizes[1];   // 2048
    const int S = in_sizes[3];   // 8192

    k_zero<<<(C_ * D_ + 255) / 256, 256>>>();
    k_accum<<<S / 2, 256>>>(xs, ys);
    k_stats<<<C_, 128>>>();
    k_main<<<N / QB, 512>>>(xq, yq, (float*)d_out, N);
}